// round 2
// baseline (speedup 1.0000x reference)
#include <cuda_runtime.h>

#define Bv    512
#define Sv    512
#define Iv    32
#define Hv    128
#define Gv    512      // 4*H
#define KSv   70       // k-columns of Whh kept in shared memory
#define KRv   58       // k-columns of Whh kept in registers (70+58=128)
#define NB    4        // batches per CTA
#define NT    256      // threads per CTA
#define NCTA  128      // 128 * 4 = 512 batches

typedef unsigned long long ull;

static __device__ __forceinline__ ull pack2(float a, float b){
    ull r; asm("mov.b64 %0, {%1,%2};" : "=l"(r) : "f"(a), "f"(b)); return r;
}
static __device__ __forceinline__ void unpack2(ull v, float& a, float& b){
    asm("mov.b64 {%0,%1}, %2;" : "=f"(a), "=f"(b) : "l"(v));
}
// Blackwell packed fp32x2 FMA: d = a*b + d (two independent fp32 lanes)
static __device__ __forceinline__ void ffma2(ull& d, ull a, ull b){
    asm("fma.rn.f32x2 %0, %1, %2, %0;" : "+l"(d) : "l"(a), "l"(b));
}
static __device__ __forceinline__ float sig_(float x){
    return __fdividef(1.f, 1.f + __expf(-x));
}
static __device__ __forceinline__ float tanh_(float x){
    float ax = fabsf(x);
    float t  = __expf(-2.f * ax);
    float r  = __fdividef(1.f - t, 1.f + t);
    return copysignf(r, x);
}

// ---- shared memory byte offsets (total 228352 <= 232448 max dyn smem) ----
#define OFF_WS     0          // float Ws[KSv][Gv]          143360 B
#define OFF_UNION  143360     // enc: float WihS[Iv][Gv] (65536 B)
                              // dec: ull fcW2[64][32]    (16384 B)
#define OFF_GACT   208896     // float gact[NB][Gv]           8192 B
#define OFF_HS2    217088     // ull   hs2[Hv][NB]  ({h,h})   4096 B
#define OFF_HSP    221184     // float hsp[NB][Hv]            2048 B
#define OFF_CS     223232     // float cs [NB][Hv]            2048 B
#define OFF_XS2    225280     // ull   xs2[Iv][NB] ({x,x})    1024 B
#define OFF_BIAS   226304     // float bias[Gv]               2048 B
#define SMEM_BYTES 228352

__global__ void __launch_bounds__(NT, 1) lstm_ae_kernel(
    const float* __restrict__ x,
    const float* __restrict__ eWih, const float* __restrict__ eWhh,
    const float* __restrict__ eBih, const float* __restrict__ eBhh,
    const float* __restrict__ dWih, const float* __restrict__ dWhh,
    const float* __restrict__ dBih, const float* __restrict__ dBhh,
    const float* __restrict__ fcW,  const float* __restrict__ fcB,
    float* __restrict__ out)
{
    extern __shared__ char smem[];
    float* Ws   = (float*)(smem + OFF_WS);
    float* WihS = (float*)(smem + OFF_UNION);
    ull*   fcW2 = (ull*)  (smem + OFF_UNION);
    float* gact = (float*)(smem + OFF_GACT);
    ull*   hs2  = (ull*)  (smem + OFF_HS2);
    float* hsp  = (float*)(smem + OFF_HSP);
    float* cs   = (float*)(smem + OFF_CS);
    ull*   xs2  = (ull*)  (smem + OFF_XS2);
    float* bias = (float*)(smem + OFF_BIAS);

    const int tid   = threadIdx.x;
    const int bbase = blockIdx.x * NB;
    const int gt    = tid >> 6;     // 0:i 1:f 2:g 3:o (warp-uniform)
    ull wr[KRv];                    // packed {w_g0, w_g1} register weights

    // ======================= encoder setup =======================
    for (int idx = tid; idx < Gv * KSv; idx += NT){
        int k = idx / Gv, g = idx - k * Gv;
        Ws[idx] = eWhh[g * Hv + k];
    }
    for (int idx = tid; idx < Gv * Iv; idx += NT){
        int k = idx / Gv, g = idx - k * Gv;
        WihS[idx] = eWih[g * Iv + k];
    }
    #pragma unroll
    for (int kk = 0; kk < KRv; kk++)
        wr[kk] = pack2(eWhh[(2*tid) * Hv + KSv + kk],
                       eWhh[(2*tid + 1) * Hv + KSv + kk]);
    for (int g = tid; g < Gv; g += NT) bias[g] = eBih[g] + eBhh[g];
    for (int i = tid; i < Hv * NB; i += NT){ hs2[i] = 0ull; cs[i] = 0.f; }
    __syncthreads();

    const float* xbase = x + (size_t)(bbase + (tid >> 5)) * Sv * Iv + (tid & 31);

    // ======================= encoder loop =======================
    for (int t = 0; t < Sv; t++){
        if (tid < Iv * NB){
            float xv = xbase[t * Iv];
            xs2[(tid & 31) * NB + (tid >> 5)] = pack2(xv, xv);
        }
        __syncthreads();

        ull acc0, acc1, acc2, acc3;
        { ull bb = *(const ull*)(bias + 2*tid); acc0 = bb; acc1 = bb; acc2 = bb; acc3 = bb; }

        #pragma unroll
        for (int k = 0; k < Iv; k++){
            ulonglong2 p01 = *((const ulonglong2*)(xs2 + k * NB));
            ulonglong2 p23 = *((const ulonglong2*)(xs2 + k * NB + 2));
            ull w = *(const ull*)(WihS + k * Gv + 2*tid);
            ffma2(acc0, p01.x, w); ffma2(acc1, p01.y, w);
            ffma2(acc2, p23.x, w); ffma2(acc3, p23.y, w);
        }
        #pragma unroll 10
        for (int k = 0; k < KSv; k++){
            ulonglong2 p01 = *((const ulonglong2*)(hs2 + k * NB));
            ulonglong2 p23 = *((const ulonglong2*)(hs2 + k * NB + 2));
            ull w = *(const ull*)(Ws + k * Gv + 2*tid);
            ffma2(acc0, p01.x, w); ffma2(acc1, p01.y, w);
            ffma2(acc2, p23.x, w); ffma2(acc3, p23.y, w);
        }
        #pragma unroll
        for (int kk = 0; kk < KRv; kk++){
            ulonglong2 p01 = *((const ulonglong2*)(hs2 + (KSv + kk) * NB));
            ulonglong2 p23 = *((const ulonglong2*)(hs2 + (KSv + kk) * NB + 2));
            ffma2(acc0, p01.x, wr[kk]); ffma2(acc1, p01.y, wr[kk]);
            ffma2(acc2, p23.x, wr[kk]); ffma2(acc3, p23.y, wr[kk]);
        }
        // activations -> gact[b][g]
        {
            ull av[4] = {acc0, acc1, acc2, acc3};
            #pragma unroll
            for (int b = 0; b < NB; b++){
                float a0, a1; unpack2(av[b], a0, a1);
                float v0, v1;
                if (gt == 2){ v0 = tanh_(a0); v1 = tanh_(a1); }
                else        { v0 = sig_(a0);  v1 = sig_(a1);  }
                *(float2*)(gact + b * Gv + 2*tid) = make_float2(v0, v1);
            }
        }
        __syncthreads();
        // c,h update
        #pragma unroll
        for (int it = 0; it < 2; it++){
            int item = tid + it * NT;
            int b = item >> 7, u = item & (Hv - 1);
            const float* gb = gact + b * Gv;
            float iv = gb[u], fv = gb[Hv + u], gv = gb[2*Hv + u], ov = gb[3*Hv + u];
            float cn = fv * cs[b * Hv + u] + iv * gv;
            cs[b * Hv + u] = cn;
            float hn = ov * tanh_(cn);
            hs2[u * NB + b] = pack2(hn, hn);
        }
        // no trailing sync needed: next-iter sync after x-store protects hs2/gact
    }
    __syncthreads();

    // ======================= decoder setup =======================
    // load dec_Whh split (step 0 uses inp=0 => gates = h @ Whh^T only)
    for (int idx = tid; idx < Gv * KSv; idx += NT){
        int k = idx / Gv, g = idx - k * Gv;
        Ws[idx] = dWhh[g * Hv + k];
    }
    #pragma unroll
    for (int kk = 0; kk < KRv; kk++)
        wr[kk] = pack2(dWhh[(2*tid) * Hv + KSv + kk],
                       dWhh[(2*tid + 1) * Hv + KSv + kk]);
    for (int g = tid; g < Gv; g += NT) bias[g] = dBih[g] + dBhh[g];
    for (int idx = tid; idx < 64 * 32; idx += NT){
        int o = idx & 31, k2 = idx >> 5;
        fcW2[idx] = pack2(fcW[o * Hv + 2*k2], fcW[o * Hv + 2*k2 + 1]);
    }
    float fcbv = (tid < Iv * NB) ? fcB[tid & 31] : 0.f;
    float* outbase = out + (size_t)(bbase + (tid >> 5)) * Sv * Iv + (tid & 31);
    // hs2 currently holds enc_h; cs holds enc_c (never modified in decoder)
    __syncthreads();

    // ======================= decoder loop =======================
    for (int t = 0; t < Sv; t++){
        ull acc0, acc1, acc2, acc3;
        { ull bb = *(const ull*)(bias + 2*tid); acc0 = bb; acc1 = bb; acc2 = bb; acc3 = bb; }

        #pragma unroll 10
        for (int k = 0; k < KSv; k++){
            ulonglong2 p01 = *((const ulonglong2*)(hs2 + k * NB));
            ulonglong2 p23 = *((const ulonglong2*)(hs2 + k * NB + 2));
            ull w = *(const ull*)(Ws + k * Gv + 2*tid);
            ffma2(acc0, p01.x, w); ffma2(acc1, p01.y, w);
            ffma2(acc2, p23.x, w); ffma2(acc3, p23.y, w);
        }
        #pragma unroll
        for (int kk = 0; kk < KRv; kk++){
            ulonglong2 p01 = *((const ulonglong2*)(hs2 + (KSv + kk) * NB));
            ulonglong2 p23 = *((const ulonglong2*)(hs2 + (KSv + kk) * NB + 2));
            ffma2(acc0, p01.x, wr[kk]); ffma2(acc1, p01.y, wr[kk]);
            ffma2(acc2, p23.x, wr[kk]); ffma2(acc3, p23.y, wr[kk]);
        }
        {
            ull av[4] = {acc0, acc1, acc2, acc3};
            #pragma unroll
            for (int b = 0; b < NB; b++){
                float a0, a1; unpack2(av[b], a0, a1);
                float v0, v1;
                if (gt == 2){ v0 = tanh_(a0); v1 = tanh_(a1); }
                else        { v0 = sig_(a0);  v1 = sig_(a1);  }
                *(float2*)(gact + b * Gv + 2*tid) = make_float2(v0, v1);
            }
        }
        __syncthreads();
        // h update: cell input is ALWAYS enc_c (cs), never written back
        #pragma unroll
        for (int it = 0; it < 2; it++){
            int item = tid + it * NT;
            int b = item >> 7, u = item & (Hv - 1);
            const float* gb = gact + b * Gv;
            float iv = gb[u], fv = gb[Hv + u], gv = gb[2*Hv + u], ov = gb[3*Hv + u];
            float cn = fv * cs[b * Hv + u] + iv * gv;
            float hn = ov * tanh_(cn);
            hs2[u * NB + b] = pack2(hn, hn);
            hsp[b * Hv + u] = hn;
        }
        __syncthreads();
        // fc: frame = h_new @ fcW^T + fcb
        if (tid < Iv * NB){
            int b = tid >> 5, o = tid & 31;
            ull s = 0ull;
            #pragma unroll
            for (int k2 = 0; k2 < Hv / 2; k2++){
                ull h2 = *(const ull*)(hsp + b * Hv + 2*k2);
                ffma2(s, h2, fcW2[k2 * 32 + o]);
            }
            float s0, s1; unpack2(s, s0, s1);
            outbase[t * Iv] = s0 + s1 + fcbv;
        }
        if (t == 0){
            // in place: Whh -> Whh + Wih (steps >=1 have inp == h)
            for (int idx = tid; idx < Gv * KSv; idx += NT){
                int k = idx / Gv, g = idx - k * Gv;
                Ws[idx] += dWih[g * Hv + k];
            }
            #pragma unroll
            for (int kk = 0; kk < KRv; kk++){
                float w0, w1; unpack2(wr[kk], w0, w1);
                w0 += dWih[(2*tid) * Hv + KSv + kk];
                w1 += dWih[(2*tid + 1) * Hv + KSv + kk];
                wr[kk] = pack2(w0, w1);
            }
        }
        __syncthreads();
    }
}

extern "C" void kernel_launch(void* const* d_in, const int* in_sizes, int n_in,
                              void* d_out, int out_size)
{
    const float* x    = (const float*)d_in[0];
    const float* eWih = (const float*)d_in[1];
    const float* eWhh = (const float*)d_in[2];
    const float* eBih = (const float*)d_in[3];
    const float* eBhh = (const float*)d_in[4];
    const float* dWih = (const float*)d_in[5];
    const float* dWhh = (const float*)d_in[6];
    const float* dBih = (const float*)d_in[7];
    const float* dBhh = (const float*)d_in[8];
    const float* fcW  = (const float*)d_in[9];
    const float* fcB  = (const float*)d_in[10];
    float* out = (float*)d_out;

    cudaFuncSetAttribute(lstm_ae_kernel,
                         cudaFuncAttributeMaxDynamicSharedMemorySize, SMEM_BYTES);
    lstm_ae_kernel<<<NCTA, NT, SMEM_BYTES>>>(
        x, eWih, eWhh, eBih, eBhh, dWih, dWhh, dBih, dBhh, fcW, fcB, out);
}

// round 3
// speedup vs baseline: 1.0008x; 1.0008x over previous
#include <cuda_runtime.h>

#define Bv    512
#define Sv    512
#define Iv    32
#define Hv    128
#define Gv    512      // 4*H
#define KSv   70       // k-columns of Whh kept in shared memory
#define KRv   58       // k-columns of Whh kept in registers (70+58=128)
#define NB    4        // batches per CTA
#define NT    256      // threads per CTA
#define NCTA  128      // 128 * 4 = 512 batches

typedef unsigned long long ull;

static __device__ __forceinline__ ull pack2(float a, float b){
    ull r; asm("mov.b64 %0, {%1,%2};" : "=l"(r) : "f"(a), "f"(b)); return r;
}
static __device__ __forceinline__ void unpack2(ull v, float& a, float& b){
    asm("mov.b64 {%0,%1}, %2;" : "=f"(a), "=f"(b) : "l"(v));
}
// Blackwell packed fp32x2 FMA: d = a*b + d (two independent fp32 lanes)
static __device__ __forceinline__ void ffma2(ull& d, ull a, ull b){
    asm("fma.rn.f32x2 %0, %1, %2, %0;" : "+l"(d) : "l"(a), "l"(b));
}
static __device__ __forceinline__ float sig_(float x){
    return __fdividef(1.f, 1.f + __expf(-x));
}
static __device__ __forceinline__ float tanh_(float x){
    float ax = fabsf(x);
    float t  = __expf(-2.f * ax);
    float r  = __fdividef(1.f - t, 1.f + t);
    return copysignf(r, x);
}

// ---- shared memory byte offsets (total 228352 <= 232448 max dyn smem) ----
#define OFF_WS     0          // float Ws[KSv][Gv]          143360 B
#define OFF_UNION  143360     // enc: float WihS[Iv][Gv] (65536 B)
                              // dec: ull fcW2[64][32]    (16384 B)
#define OFF_GACT   208896     // float gact[NB][Gv]           8192 B
#define OFF_HS2    217088     // ull   hs2[Hv][NB]  ({h,h})   4096 B
#define OFF_HSP    221184     // float hsp[NB][Hv]            2048 B
#define OFF_CS     223232     // float cs [NB][Hv]            2048 B
#define OFF_XS2    225280     // ull   xs2[Iv][NB] ({x,x})    1024 B
#define OFF_BIAS   226304     // float bias[Gv]               2048 B
#define SMEM_BYTES 228352

__global__ void __launch_bounds__(NT, 1) lstm_ae_kernel(
    const float* __restrict__ x,
    const float* __restrict__ eWih, const float* __restrict__ eWhh,
    const float* __restrict__ eBih, const float* __restrict__ eBhh,
    const float* __restrict__ dWih, const float* __restrict__ dWhh,
    const float* __restrict__ dBih, const float* __restrict__ dBhh,
    const float* __restrict__ fcW,  const float* __restrict__ fcB,
    float* __restrict__ out)
{
    extern __shared__ char smem[];
    float* Ws   = (float*)(smem + OFF_WS);
    float* WihS = (float*)(smem + OFF_UNION);
    ull*   fcW2 = (ull*)  (smem + OFF_UNION);
    float* gact = (float*)(smem + OFF_GACT);
    ull*   hs2  = (ull*)  (smem + OFF_HS2);
    float* hsp  = (float*)(smem + OFF_HSP);
    float* cs   = (float*)(smem + OFF_CS);
    ull*   xs2  = (ull*)  (smem + OFF_XS2);
    float* bias = (float*)(smem + OFF_BIAS);

    const int tid   = threadIdx.x;
    const int bbase = blockIdx.x * NB;
    const int gt    = tid >> 6;     // 0:i 1:f 2:g 3:o (warp-uniform)
    ull wr[KRv];                    // packed {w_g0, w_g1} register weights

    // ======================= encoder setup =======================
    for (int idx = tid; idx < Gv * KSv; idx += NT){
        int k = idx / Gv, g = idx - k * Gv;
        Ws[idx] = eWhh[g * Hv + k];
    }
    for (int idx = tid; idx < Gv * Iv; idx += NT){
        int k = idx / Gv, g = idx - k * Gv;
        WihS[idx] = eWih[g * Iv + k];
    }
    #pragma unroll
    for (int kk = 0; kk < KRv; kk++)
        wr[kk] = pack2(eWhh[(2*tid) * Hv + KSv + kk],
                       eWhh[(2*tid + 1) * Hv + KSv + kk]);
    for (int g = tid; g < Gv; g += NT) bias[g] = eBih[g] + eBhh[g];
    for (int i = tid; i < Hv * NB; i += NT){ hs2[i] = 0ull; cs[i] = 0.f; }
    __syncthreads();

    const float* xbase = x + (size_t)(bbase + (tid >> 5)) * Sv * Iv + (tid & 31);

    // ======================= encoder loop =======================
    for (int t = 0; t < Sv; t++){
        if (tid < Iv * NB){
            float xv = xbase[t * Iv];
            xs2[(tid & 31) * NB + (tid >> 5)] = pack2(xv, xv);
        }
        __syncthreads();

        ull acc0, acc1, acc2, acc3;
        { ull bb = *(const ull*)(bias + 2*tid); acc0 = bb; acc1 = bb; acc2 = bb; acc3 = bb; }

        #pragma unroll
        for (int k = 0; k < Iv; k++){
            ulonglong2 p01 = *((const ulonglong2*)(xs2 + k * NB));
            ulonglong2 p23 = *((const ulonglong2*)(xs2 + k * NB + 2));
            ull w = *(const ull*)(WihS + k * Gv + 2*tid);
            ffma2(acc0, p01.x, w); ffma2(acc1, p01.y, w);
            ffma2(acc2, p23.x, w); ffma2(acc3, p23.y, w);
        }
        #pragma unroll 10
        for (int k = 0; k < KSv; k++){
            ulonglong2 p01 = *((const ulonglong2*)(hs2 + k * NB));
            ulonglong2 p23 = *((const ulonglong2*)(hs2 + k * NB + 2));
            ull w = *(const ull*)(Ws + k * Gv + 2*tid);
            ffma2(acc0, p01.x, w); ffma2(acc1, p01.y, w);
            ffma2(acc2, p23.x, w); ffma2(acc3, p23.y, w);
        }
        #pragma unroll
        for (int kk = 0; kk < KRv; kk++){
            ulonglong2 p01 = *((const ulonglong2*)(hs2 + (KSv + kk) * NB));
            ulonglong2 p23 = *((const ulonglong2*)(hs2 + (KSv + kk) * NB + 2));
            ffma2(acc0, p01.x, wr[kk]); ffma2(acc1, p01.y, wr[kk]);
            ffma2(acc2, p23.x, wr[kk]); ffma2(acc3, p23.y, wr[kk]);
        }
        // activations -> gact[b][g]
        {
            ull av[4] = {acc0, acc1, acc2, acc3};
            #pragma unroll
            for (int b = 0; b < NB; b++){
                float a0, a1; unpack2(av[b], a0, a1);
                float v0, v1;
                if (gt == 2){ v0 = tanh_(a0); v1 = tanh_(a1); }
                else        { v0 = sig_(a0);  v1 = sig_(a1);  }
                *(float2*)(gact + b * Gv + 2*tid) = make_float2(v0, v1);
            }
        }
        __syncthreads();
        // c,h update
        #pragma unroll
        for (int it = 0; it < 2; it++){
            int item = tid + it * NT;
            int b = item >> 7, u = item & (Hv - 1);
            const float* gb = gact + b * Gv;
            float iv = gb[u], fv = gb[Hv + u], gv = gb[2*Hv + u], ov = gb[3*Hv + u];
            float cn = fv * cs[b * Hv + u] + iv * gv;
            cs[b * Hv + u] = cn;
            float hn = ov * tanh_(cn);
            hs2[u * NB + b] = pack2(hn, hn);
        }
        // no trailing sync needed: next-iter sync after x-store protects hs2/gact
    }
    __syncthreads();

    // ======================= decoder setup =======================
    // load dec_Whh split (step 0 uses inp=0 => gates = h @ Whh^T only)
    for (int idx = tid; idx < Gv * KSv; idx += NT){
        int k = idx / Gv, g = idx - k * Gv;
        Ws[idx] = dWhh[g * Hv + k];
    }
    #pragma unroll
    for (int kk = 0; kk < KRv; kk++)
        wr[kk] = pack2(dWhh[(2*tid) * Hv + KSv + kk],
                       dWhh[(2*tid + 1) * Hv + KSv + kk]);
    for (int g = tid; g < Gv; g += NT) bias[g] = dBih[g] + dBhh[g];
    for (int idx = tid; idx < 64 * 32; idx += NT){
        int o = idx & 31, k2 = idx >> 5;
        fcW2[idx] = pack2(fcW[o * Hv + 2*k2], fcW[o * Hv + 2*k2 + 1]);
    }
    float fcbv = (tid < Iv * NB) ? fcB[tid & 31] : 0.f;
    float* outbase = out + (size_t)(bbase + (tid >> 5)) * Sv * Iv + (tid & 31);
    // hs2 currently holds enc_h; cs holds enc_c (never modified in decoder)
    __syncthreads();

    // ======================= decoder loop =======================
    for (int t = 0; t < Sv; t++){
        ull acc0, acc1, acc2, acc3;
        { ull bb = *(const ull*)(bias + 2*tid); acc0 = bb; acc1 = bb; acc2 = bb; acc3 = bb; }

        #pragma unroll 10
        for (int k = 0; k < KSv; k++){
            ulonglong2 p01 = *((const ulonglong2*)(hs2 + k * NB));
            ulonglong2 p23 = *((const ulonglong2*)(hs2 + k * NB + 2));
            ull w = *(const ull*)(Ws + k * Gv + 2*tid);
            ffma2(acc0, p01.x, w); ffma2(acc1, p01.y, w);
            ffma2(acc2, p23.x, w); ffma2(acc3, p23.y, w);
        }
        #pragma unroll
        for (int kk = 0; kk < KRv; kk++){
            ulonglong2 p01 = *((const ulonglong2*)(hs2 + (KSv + kk) * NB));
            ulonglong2 p23 = *((const ulonglong2*)(hs2 + (KSv + kk) * NB + 2));
            ffma2(acc0, p01.x, wr[kk]); ffma2(acc1, p01.y, wr[kk]);
            ffma2(acc2, p23.x, wr[kk]); ffma2(acc3, p23.y, wr[kk]);
        }
        {
            ull av[4] = {acc0, acc1, acc2, acc3};
            #pragma unroll
            for (int b = 0; b < NB; b++){
                float a0, a1; unpack2(av[b], a0, a1);
                float v0, v1;
                if (gt == 2){ v0 = tanh_(a0); v1 = tanh_(a1); }
                else        { v0 = sig_(a0);  v1 = sig_(a1);  }
                *(float2*)(gact + b * Gv + 2*tid) = make_float2(v0, v1);
            }
        }
        __syncthreads();
        // h update: cell input is ALWAYS enc_c (cs), never written back
        #pragma unroll
        for (int it = 0; it < 2; it++){
            int item = tid + it * NT;
            int b = item >> 7, u = item & (Hv - 1);
            const float* gb = gact + b * Gv;
            float iv = gb[u], fv = gb[Hv + u], gv = gb[2*Hv + u], ov = gb[3*Hv + u];
            float cn = fv * cs[b * Hv + u] + iv * gv;
            float hn = ov * tanh_(cn);
            hs2[u * NB + b] = pack2(hn, hn);
            hsp[b * Hv + u] = hn;
        }
        __syncthreads();
        // fc: frame = h_new @ fcW^T + fcb
        if (tid < Iv * NB){
            int b = tid >> 5, o = tid & 31;
            ull s = 0ull;
            #pragma unroll
            for (int k2 = 0; k2 < Hv / 2; k2++){
                ull h2 = *(const ull*)(hsp + b * Hv + 2*k2);
                ffma2(s, h2, fcW2[k2 * 32 + o]);
            }
            float s0, s1; unpack2(s, s0, s1);
            outbase[t * Iv] = s0 + s1 + fcbv;
        }
        if (t == 0){
            // in place: Whh -> Whh + Wih (steps >=1 have inp == h)
            for (int idx = tid; idx < Gv * KSv; idx += NT){
                int k = idx / Gv, g = idx - k * Gv;
                Ws[idx] += dWih[g * Hv + k];
            }
            #pragma unroll
            for (int kk = 0; kk < KRv; kk++){
                float w0, w1; unpack2(wr[kk], w0, w1);
                w0 += dWih[(2*tid) * Hv + KSv + kk];
                w1 += dWih[(2*tid + 1) * Hv + KSv + kk];
                wr[kk] = pack2(w0, w1);
            }
        }
        __syncthreads();
    }
}

extern "C" void kernel_launch(void* const* d_in, const int* in_sizes, int n_in,
                              void* d_out, int out_size)
{
    const float* x    = (const float*)d_in[0];
    const float* eWih = (const float*)d_in[1];
    const float* eWhh = (const float*)d_in[2];
    const float* eBih = (const float*)d_in[3];
    const float* eBhh = (const float*)d_in[4];
    const float* dWih = (const float*)d_in[5];
    const float* dWhh = (const float*)d_in[6];
    const float* dBih = (const float*)d_in[7];
    const float* dBhh = (const float*)d_in[8];
    const float* fcW  = (const float*)d_in[9];
    const float* fcB  = (const float*)d_in[10];
    float* out = (float*)d_out;

    cudaFuncSetAttribute(lstm_ae_kernel,
                         cudaFuncAttributeMaxDynamicSharedMemorySize, SMEM_BYTES);
    lstm_ae_kernel<<<NCTA, NT, SMEM_BYTES>>>(
        x, eWih, eWhh, eBih, eBhh, dWih, dWhh, dBih, dBhh, fcW, fcB, out);
}

// round 4
// speedup vs baseline: 1.1640x; 1.1631x over previous
#include <cuda_runtime.h>

#define Sv    512
#define Iv    32
#define Hv    128
#define Gv    512      // 4*H
#define KSv   72       // k-columns of Whh kept in shared memory (0..71)
#define KRv   56       // k-columns of Whh kept in registers (72..127)
#define NB    4        // batches per CTA
#define NT    256      // threads per CTA
#define NCTA  128      // 128 * 4 = 512 batches

typedef unsigned long long ull;

static __device__ __forceinline__ ull pack2(float a, float b){
    ull r; asm("mov.b64 %0, {%1,%2};" : "=l"(r) : "f"(a), "f"(b)); return r;
}
static __device__ __forceinline__ ull dup2(float a){
    ull r; asm("mov.b64 %0, {%1,%1};" : "=l"(r) : "f"(a)); return r;
}
static __device__ __forceinline__ void unpack2(ull v, float& a, float& b){
    asm("mov.b64 {%0,%1}, %2;" : "=f"(a), "=f"(b) : "l"(v));
}
// Blackwell packed fp32x2 FMA: d = a*b + d (two independent fp32 lanes)
static __device__ __forceinline__ void ffma2(ull& d, ull a, ull b){
    asm("fma.rn.f32x2 %0, %1, %2, %0;" : "+l"(d) : "l"(a), "l"(b));
}
static __device__ __forceinline__ float sig_(float x){
    return __fdividef(1.f, 1.f + __expf(-x));
}
static __device__ __forceinline__ float tanh_(float x){
    float ax = fabsf(x);
    float t  = __expf(-2.f * ax);
    float r  = __fdividef(1.f - t, 1.f + t);
    return copysignf(r, x);
}

// ---- shared memory byte offsets (total 229760 <= 232448 max dyn smem) ----
// enc Ws rows: 0..31 = Wih[k], 32..103 = Whh[k=0..71]   (104 rows * 2048B)
// dec Ws rows: 0..71 = Whh/Wsum[k=0..71]; fcW2 overlays rows 72..79
#define OFF_WS     0          // float Ws[104][Gv]          212992 B
#define OFF_FCW    147456     // ull fcW2[64][32] (dec only, overlay) 16384 B
#define OFF_GACT   212992     // float gact[NB][Gv]           8192 B
#define OFF_HS4    221184     // float hs4[Hv][NB]            2048 B (batch-paired h)
#define OFF_HS2D   223232     // ull   hs2d[KRv][NB] ({h,h})  1792 B (+pad)
#define OFF_HSP    225152     // float hsp[NB][Hv]            2048 B
#define OFF_CS     227200     // float cs [NB][Hv]            2048 B
#define OFF_XS4    229248     // float xs4[Iv][NB]             512 B
#define SMEM_BYTES 229760

__global__ void __launch_bounds__(NT, 1) lstm_ae_kernel(
    const float* __restrict__ x,
    const float* __restrict__ eWih, const float* __restrict__ eWhh,
    const float* __restrict__ eBih, const float* __restrict__ eBhh,
    const float* __restrict__ dWih, const float* __restrict__ dWhh,
    const float* __restrict__ dBih, const float* __restrict__ dBhh,
    const float* __restrict__ fcW,  const float* __restrict__ fcB,
    float* __restrict__ out)
{
    extern __shared__ char smem[];
    float* Ws   = (float*)(smem + OFF_WS);
    ull*   fcW2 = (ull*)  (smem + OFF_FCW);
    float* gact = (float*)(smem + OFF_GACT);
    float* hs4  = (float*)(smem + OFF_HS4);
    ull*   hs2d = (ull*)  (smem + OFF_HS2D);
    float* hsp  = (float*)(smem + OFF_HSP);
    float* cs   = (float*)(smem + OFF_CS);
    float* xs4  = (float*)(smem + OFF_XS4);

    const int tid   = threadIdx.x;
    const int bbase = blockIdx.x * NB;
    const int gt    = tid >> 6;     // 0:i 1:f 2:g 3:o (warp-uniform)
    ull wr[KRv];                    // packed {w_g0, w_g1} register weights

    // ======================= encoder setup =======================
    for (int idx = tid; idx < Gv * (Iv + KSv); idx += NT){
        int r = idx / Gv, g = idx - r * Gv;
        Ws[idx] = (r < Iv) ? eWih[g * Iv + r] : eWhh[g * Hv + (r - Iv)];
    }
    #pragma unroll
    for (int kk = 0; kk < KRv; kk++)
        wr[kk] = pack2(eWhh[(2*tid) * Hv + KSv + kk],
                       eWhh[(2*tid + 1) * Hv + KSv + kk]);
    ull bd0 = dup2(eBih[2*tid]     + eBhh[2*tid]);
    ull bd1 = dup2(eBih[2*tid + 1] + eBhh[2*tid + 1]);
    for (int i = tid; i < Hv * NB; i += NT){ hs4[i] = 0.f; cs[i] = 0.f; }
    for (int i = tid; i < KRv * NB; i += NT) hs2d[i] = 0ull;
    __syncthreads();

    const float* xbase = x + (size_t)(bbase + (tid >> 5)) * Sv * Iv + (tid & 31);
    const float* wp = Ws + 2*tid;

    // ======================= encoder loop =======================
    for (int t = 0; t < Sv; t++){
        if (tid < Iv * NB)
            xs4[(tid & 31) * NB + (tid >> 5)] = xbase[t * Iv];
        __syncthreads();

        // batch-paired accumulators (smem-weight portion), bias preloaded
        ull p00 = bd0, p01 = bd0, p10 = bd1, p11 = bd1;
        // gate-paired accumulators (register-weight portion)
        ull q0 = 0ull, q1 = 0ull, q2 = 0ull, q3 = 0ull;

        #pragma unroll 8
        for (int r = 0; r < Iv; r++){
            ulonglong2 h = *(const ulonglong2*)(xs4 + r * NB);   // {b0,b1},{b2,b3}
            float2 w = *(const float2*)(wp + r * Gv);
            ull wd0 = dup2(w.x), wd1 = dup2(w.y);
            ffma2(p00, h.x, wd0); ffma2(p01, h.y, wd0);
            ffma2(p10, h.x, wd1); ffma2(p11, h.y, wd1);
        }
        #pragma unroll 8
        for (int k = 0; k < KSv; k++){
            ulonglong2 h = *(const ulonglong2*)(hs4 + k * NB);
            float2 w = *(const float2*)(wp + (Iv + k) * Gv);
            ull wd0 = dup2(w.x), wd1 = dup2(w.y);
            ffma2(p00, h.x, wd0); ffma2(p01, h.y, wd0);
            ffma2(p10, h.x, wd1); ffma2(p11, h.y, wd1);
        }
        #pragma unroll
        for (int kk = 0; kk < KRv; kk++){
            ulonglong2 d01 = *(const ulonglong2*)(hs2d + kk * NB);
            ulonglong2 d23 = *(const ulonglong2*)(hs2d + kk * NB + 2);
            ffma2(q0, d01.x, wr[kk]); ffma2(q1, d01.y, wr[kk]);
            ffma2(q2, d23.x, wr[kk]); ffma2(q3, d23.y, wr[kk]);
        }
        // merge both accumulator sets + activations -> gact[b][g]
        {
            float a00,a01,a02,a03,a10,a11,a12,a13;
            unpack2(p00, a00, a01); unpack2(p01, a02, a03);
            unpack2(p10, a10, a11); unpack2(p11, a12, a13);
            float b00,b10,b01,b11,b02,b12,b03,b13;
            unpack2(q0, b00, b10); unpack2(q1, b01, b11);
            unpack2(q2, b02, b12); unpack2(q3, b03, b13);
            float s0[4] = {a00+b00, a01+b01, a02+b02, a03+b03};
            float s1[4] = {a10+b10, a11+b11, a12+b12, a13+b13};
            #pragma unroll
            for (int b = 0; b < NB; b++){
                float v0, v1;
                if (gt == 2){ v0 = tanh_(s0[b]); v1 = tanh_(s1[b]); }
                else        { v0 = sig_(s0[b]);  v1 = sig_(s1[b]);  }
                *(float2*)(gact + b * Gv + 2*tid) = make_float2(v0, v1);
            }
        }
        __syncthreads();
        // c,h update
        #pragma unroll
        for (int it = 0; it < 2; it++){
            int item = tid + it * NT;
            int b = item >> 7, u = item & (Hv - 1);
            const float* gb = gact + b * Gv;
            float iv = gb[u], fv = gb[Hv + u], gv = gb[2*Hv + u], ov = gb[3*Hv + u];
            float cn = fv * cs[b * Hv + u] + iv * gv;
            cs[b * Hv + u] = cn;
            float hn = ov * tanh_(cn);
            hs4[u * NB + b] = hn;
            if (u >= KSv) hs2d[(u - KSv) * NB + b] = pack2(hn, hn);
        }
        // no trailing sync needed: next-iter sync after x-store protects hs4/gact
    }
    __syncthreads();

    // ======================= decoder setup =======================
    // step 0 uses inp=0 => gates = h @ Whh^T only
    for (int idx = tid; idx < Gv * KSv; idx += NT){
        int r = idx / Gv, g = idx - r * Gv;
        Ws[idx] = dWhh[g * Hv + r];
    }
    #pragma unroll
    for (int kk = 0; kk < KRv; kk++)
        wr[kk] = pack2(dWhh[(2*tid) * Hv + KSv + kk],
                       dWhh[(2*tid + 1) * Hv + KSv + kk]);
    bd0 = dup2(dBih[2*tid]     + dBhh[2*tid]);
    bd1 = dup2(dBih[2*tid + 1] + dBhh[2*tid + 1]);
    for (int idx = tid; idx < 64 * 32; idx += NT){
        int o = idx & 31, k2 = idx >> 5;
        fcW2[idx] = pack2(fcW[o * Hv + 2*k2], fcW[o * Hv + 2*k2 + 1]);
    }
    float fcbv = (tid < Iv * NB) ? fcB[tid & 31] : 0.f;
    float* outbase = out + (size_t)(bbase + (tid >> 5)) * Sv * Iv + (tid & 31);
    // hs4/hs2d currently hold enc_h; cs holds enc_c (never modified in decoder)
    __syncthreads();

    // ======================= decoder loop =======================
    for (int t = 0; t < Sv; t++){
        ull p00 = bd0, p01 = bd0, p10 = bd1, p11 = bd1;
        ull q0 = 0ull, q1 = 0ull, q2 = 0ull, q3 = 0ull;

        #pragma unroll 8
        for (int k = 0; k < KSv; k++){
            ulonglong2 h = *(const ulonglong2*)(hs4 + k * NB);
            float2 w = *(const float2*)(wp + k * Gv);
            ull wd0 = dup2(w.x), wd1 = dup2(w.y);
            ffma2(p00, h.x, wd0); ffma2(p01, h.y, wd0);
            ffma2(p10, h.x, wd1); ffma2(p11, h.y, wd1);
        }
        #pragma unroll
        for (int kk = 0; kk < KRv; kk++){
            ulonglong2 d01 = *(const ulonglong2*)(hs2d + kk * NB);
            ulonglong2 d23 = *(const ulonglong2*)(hs2d + kk * NB + 2);
            ffma2(q0, d01.x, wr[kk]); ffma2(q1, d01.y, wr[kk]);
            ffma2(q2, d23.x, wr[kk]); ffma2(q3, d23.y, wr[kk]);
        }
        {
            float a00,a01,a02,a03,a10,a11,a12,a13;
            unpack2(p00, a00, a01); unpack2(p01, a02, a03);
            unpack2(p10, a10, a11); unpack2(p11, a12, a13);
            float b00,b10,b01,b11,b02,b12,b03,b13;
            unpack2(q0, b00, b10); unpack2(q1, b01, b11);
            unpack2(q2, b02, b12); unpack2(q3, b03, b13);
            float s0[4] = {a00+b00, a01+b01, a02+b02, a03+b03};
            float s1[4] = {a10+b10, a11+b11, a12+b12, a13+b13};
            #pragma unroll
            for (int b = 0; b < NB; b++){
                float v0, v1;
                if (gt == 2){ v0 = tanh_(s0[b]); v1 = tanh_(s1[b]); }
                else        { v0 = sig_(s0[b]);  v1 = sig_(s1[b]);  }
                *(float2*)(gact + b * Gv + 2*tid) = make_float2(v0, v1);
            }
        }
        __syncthreads();
        // h update: cell input is ALWAYS enc_c (cs), never written back
        #pragma unroll
        for (int it = 0; it < 2; it++){
            int item = tid + it * NT;
            int b = item >> 7, u = item & (Hv - 1);
            const float* gb = gact + b * Gv;
            float iv = gb[u], fv = gb[Hv + u], gv = gb[2*Hv + u], ov = gb[3*Hv + u];
            float cn = fv * cs[b * Hv + u] + iv * gv;
            float hn = ov * tanh_(cn);
            hs4[u * NB + b] = hn;
            if (u >= KSv) hs2d[(u - KSv) * NB + b] = pack2(hn, hn);
            hsp[b * Hv + u] = hn;
        }
        __syncthreads();
        // fc: frame = h_new @ fcW^T + fcb
        if (tid < Iv * NB){
            int b = tid >> 5, o = tid & 31;
            ull s = 0ull;
            #pragma unroll
            for (int k2 = 0; k2 < Hv / 2; k2++){
                ull h2 = *(const ull*)(hsp + b * Hv + 2*k2);
                ffma2(s, h2, fcW2[k2 * 32 + o]);
            }
            float s0, s1; unpack2(s, s0, s1);
            outbase[t * Iv] = s0 + s1 + fcbv;
        }
        if (t == 0){
            // in place: Whh -> Whh + Wih (steps >=1 have inp == h)
            for (int idx = tid; idx < Gv * KSv; idx += NT){
                int r = idx / Gv, g = idx - r * Gv;
                Ws[idx] += dWih[g * Hv + r];
            }
            #pragma unroll
            for (int kk = 0; kk < KRv; kk++){
                float w0, w1; unpack2(wr[kk], w0, w1);
                w0 += dWih[(2*tid) * Hv + KSv + kk];
                w1 += dWih[(2*tid + 1) * Hv + KSv + kk];
                wr[kk] = pack2(w0, w1);
            }
        }
        __syncthreads();
    }
}

extern "C" void kernel_launch(void* const* d_in, const int* in_sizes, int n_in,
                              void* d_out, int out_size)
{
    const float* x    = (const float*)d_in[0];
    const float* eWih = (const float*)d_in[1];
    const float* eWhh = (const float*)d_in[2];
    const float* eBih = (const float*)d_in[3];
    const float* eBhh = (const float*)d_in[4];
    const float* dWih = (const float*)d_in[5];
    const float* dWhh = (const float*)d_in[6];
    const float* dBih = (const float*)d_in[7];
    const float* dBhh = (const float*)d_in[8];
    const float* fcW  = (const float*)d_in[9];
    const float* fcB  = (const float*)d_in[10];
    float* out = (float*)d_out;

    cudaFuncSetAttribute(lstm_ae_kernel,
                         cudaFuncAttributeMaxDynamicSharedMemorySize, SMEM_BYTES);
    lstm_ae_kernel<<<NCTA, NT, SMEM_BYTES>>>(
        x, eWih, eWhh, eBih, eBhh, dWih, dWhh, dBih, dBhh, fcW, fcB, out);
}

// round 5
// speedup vs baseline: 1.1709x; 1.0059x over previous
#include <cuda_runtime.h>

#define Sv    512
#define Iv    32
#define Hv    128
#define Gv    512      // 4*H
#define NB    4        // batches per CTA
#define NT    512      // threads per CTA (two halves of 256)
#define NCTA  128      // 128 * 4 = 512 batches
#define KRv   32       // register weight rows PER HALF (64 total)

// enc rows (160 = 32 x + 128 h):
//   low  half: smem x k=0..31 (Ws rows 0..31) + h k=0..15 (rows 32..47); reg h k=16..47
//   high half: smem h k=48..95 (rows 48..95);                            reg h k=96..127
// dec rows (128 h):
//   low  half: smem h k=0..31  (rows 0..31);  reg h k=32..63
//   high half: smem h k=64..95 (rows 32..63); reg h k=96..127

typedef unsigned long long ull;

static __device__ __forceinline__ ull pack2(float a, float b){
    ull r; asm("mov.b64 %0, {%1,%2};" : "=l"(r) : "f"(a), "f"(b)); return r;
}
static __device__ __forceinline__ ull dup2(float a){
    ull r; asm("mov.b64 %0, {%1,%1};" : "=l"(r) : "f"(a)); return r;
}
static __device__ __forceinline__ void unpack2(ull v, float& a, float& b){
    asm("mov.b64 {%0,%1}, %2;" : "=f"(a), "=f"(b) : "l"(v));
}
// Blackwell packed fp32x2 FMA: d = a*b + d (two independent fp32 lanes)
static __device__ __forceinline__ void ffma2(ull& d, ull a, ull b){
    asm("fma.rn.f32x2 %0, %1, %2, %0;" : "+l"(d) : "l"(a), "l"(b));
}
static __device__ __forceinline__ float sig_(float x){
    return __fdividef(1.f, 1.f + __expf(-x));
}
static __device__ __forceinline__ float tanh_(float x){
    float ax = fabsf(x);
    float t  = __expf(-2.f * ax);
    float r  = __fdividef(1.f - t, 1.f + t);
    return copysignf(r, x);
}

// ---- shared memory byte offsets (total 231936 <= 232448) ----
#define OFF_WS     0          // float Ws[96][Gv]            196608 B
#define OFF_FCW    131072     // ull fcW2[64][32] overlay on Ws rows 64.. (dec only)
#define OFF_PACT   196608     // float pact[2][512][4]        16384 B
#define OFF_GACT   212992     // float gact[NB][Gv]            8192 B
#define OFF_HS4    221184     // float hs4[Hv][NB]             2048 B (batch-grouped h)
#define OFF_HS2D   223232     // ull   hs2d[Hv][NB] ({h,h})    4096 B
#define OFF_HSP    227328     // float hsp[NB][Hv]             2048 B
#define OFF_CS     229376     // float cs [NB][Hv]             2048 B
#define OFF_XS4    231424     // float xs4[Iv][NB]              512 B
#define SMEM_BYTES 231936

#define MAC4(PH, PW)                                                     \
    {   ulonglong2 h = *(const ulonglong2*)(PH);                         \
        float2 w = *(const float2*)(PW);                                 \
        ull wd0 = dup2(w.x), wd1 = dup2(w.y);                            \
        ffma2(p00, h.x, wd0); ffma2(p01, h.y, wd0);                      \
        ffma2(p10, h.x, wd1); ffma2(p11, h.y, wd1); }

__global__ void __launch_bounds__(NT, 1) lstm_ae_kernel(
    const float* __restrict__ x,
    const float* __restrict__ eWih, const float* __restrict__ eWhh,
    const float* __restrict__ eBih, const float* __restrict__ eBhh,
    const float* __restrict__ dWih, const float* __restrict__ dWhh,
    const float* __restrict__ dBih, const float* __restrict__ dBhh,
    const float* __restrict__ fcW,  const float* __restrict__ fcB,
    float* __restrict__ out)
{
    extern __shared__ char smem[];
    float* Ws   = (float*)(smem + OFF_WS);
    ull*   fcW2 = (ull*)  (smem + OFF_FCW);
    float4* pact= (float4*)(smem + OFF_PACT);   // [2][512]
    float* gact = (float*)(smem + OFF_GACT);
    float* hs4  = (float*)(smem + OFF_HS4);
    ull*   hs2d = (ull*)  (smem + OFF_HS2D);
    float* hsp  = (float*)(smem + OFF_HSP);
    float* cs   = (float*)(smem + OFF_CS);
    float* xs4  = (float*)(smem + OFF_XS4);

    const int tid  = threadIdx.x;
    const int t2   = tid & 255;       // gate pair index: gates 2*t2, 2*t2+1
    const int half = tid >> 8;        // 0 = low rows, 1 = high rows
    const int gt   = t2 >> 6;         // 0:i 1:f 2:g 3:o
    const int bbase= blockIdx.x * NB;
    ull wr[KRv];

    // ======================= encoder setup =======================
    for (int idx = tid; idx < Gv * 96; idx += NT){
        int r = idx >> 9, g = idx & (Gv - 1);
        float v;
        if (r < 32)      v = eWih[g * Iv + r];
        else if (r < 48) v = eWhh[g * Hv + (r - 32)];
        else             v = eWhh[g * Hv + r];
        Ws[idx] = v;
    }
    {
        const int kb = half ? 96 : 16;
        #pragma unroll
        for (int kk = 0; kk < KRv; kk++)
            wr[kk] = pack2(eWhh[(2*t2) * Hv + kb + kk],
                           eWhh[(2*t2 + 1) * Hv + kb + kk]);
    }
    ull bd0 = 0ull, bd1 = 0ull;
    if (!half){
        bd0 = dup2(eBih[2*t2]     + eBhh[2*t2]);
        bd1 = dup2(eBih[2*t2 + 1] + eBhh[2*t2 + 1]);
    }
    { hs4[tid] = 0.f; cs[tid] = 0.f; hs2d[tid] = 0ull; }   // NT == Hv*NB
    __syncthreads();

    const float* xbase = x + (size_t)(bbase + (tid >> 5)) * Sv * Iv + (tid & 31);
    const float* wp = Ws + 2*t2;

    // ======================= encoder loop =======================
    for (int t = 0; t < Sv; t++){
        if (tid < Iv * NB)
            xs4[(tid & 31) * NB + (tid >> 5)] = xbase[t * Iv];
        __syncthreads();                                   // B1

        ull p00 = bd0, p01 = bd0, p10 = bd1, p11 = bd1;    // batch-paired (smem rows)
        ull q0 = 0ull, q1 = 0ull, q2 = 0ull, q3 = 0ull;    // gate-paired  (reg rows)

        if (!half){
            #pragma unroll 8
            for (int r = 0; r < Iv; r++)
                MAC4(xs4 + r * NB, wp + r * Gv);
            #pragma unroll 8
            for (int j = 0; j < 16; j++)
                MAC4(hs4 + j * NB, wp + (32 + j) * Gv);
        } else {
            #pragma unroll 8
            for (int j = 0; j < 48; j++)
                MAC4(hs4 + (48 + j) * NB, wp + (48 + j) * Gv);
        }
        {
            const int kb = half ? 96 : 16;
            #pragma unroll
            for (int kk = 0; kk < KRv; kk++){
                ulonglong2 d01 = *(const ulonglong2*)(hs2d + (kb + kk) * NB);
                ulonglong2 d23 = *(const ulonglong2*)(hs2d + (kb + kk) * NB + 2);
                ffma2(q0, d01.x, wr[kk]); ffma2(q1, d01.y, wr[kk]);
                ffma2(q2, d23.x, wr[kk]); ffma2(q3, d23.y, wr[kk]);
            }
        }
        // merge local partials, exchange with partner half
        float s0[4], s1[4];
        unpack2(p00, s0[0], s0[1]); unpack2(p01, s0[2], s0[3]);
        unpack2(p10, s1[0], s1[1]); unpack2(p11, s1[2], s1[3]);
        {   float u0, u1;
            unpack2(q0, u0, u1); s0[0] += u0; s1[0] += u1;
            unpack2(q1, u0, u1); s0[1] += u0; s1[1] += u1;
            unpack2(q2, u0, u1); s0[2] += u0; s1[2] += u1;
            unpack2(q3, u0, u1); s0[3] += u0; s1[3] += u1; }
        pact[tid]       = make_float4(s0[0], s1[0], s0[1], s1[1]);
        pact[512 + tid] = make_float4(s0[2], s1[2], s0[3], s1[3]);
        __syncthreads();                                   // B2
        {
            float4 pr = pact[half * 512 + (tid ^ 256)];
            int b0i = half * 2;
            float m00 = s0[b0i]     + pr.x, m10 = s1[b0i]     + pr.y;
            float m01 = s0[b0i + 1] + pr.z, m11 = s1[b0i + 1] + pr.w;
            float v00, v10, v01, v11;
            if (gt == 2){ v00 = tanh_(m00); v10 = tanh_(m10); v01 = tanh_(m01); v11 = tanh_(m11); }
            else        { v00 = sig_(m00);  v10 = sig_(m10);  v01 = sig_(m01);  v11 = sig_(m11);  }
            *(float2*)(gact + b0i * Gv + 2*t2)       = make_float2(v00, v10);
            *(float2*)(gact + (b0i + 1) * Gv + 2*t2) = make_float2(v01, v11);
        }
        __syncthreads();                                   // B3
        {   // c,h update: one (b,u) item per thread
            int b = tid >> 7, u = tid & (Hv - 1);
            const float* gb = gact + b * Gv;
            float iv = gb[u], fv = gb[Hv + u], gvv = gb[2*Hv + u], ov = gb[3*Hv + u];
            float cn = fv * cs[b * Hv + u] + iv * gvv;
            cs[b * Hv + u] = cn;
            float hn = ov * tanh_(cn);
            hs4[u * NB + b]  = hn;
            hs2d[u * NB + b] = pack2(hn, hn);
        }
        // next-iter B1 protects hs4/hs2d
    }
    __syncthreads();

    // ======================= decoder setup =======================
    // step 0 uses inp=0 => gates = h @ Whh^T only
    for (int idx = tid; idx < Gv * 64; idx += NT){
        int r = idx >> 9, g = idx & (Gv - 1);
        Ws[idx] = (r < 32) ? dWhh[g * Hv + r] : dWhh[g * Hv + (r + 32)];
    }
    const int kbd = half ? 96 : 32;
    #pragma unroll
    for (int kk = 0; kk < KRv; kk++)
        wr[kk] = pack2(dWhh[(2*t2) * Hv + kbd + kk],
                       dWhh[(2*t2 + 1) * Hv + kbd + kk]);
    if (!half){
        bd0 = dup2(dBih[2*t2]     + dBhh[2*t2]);
        bd1 = dup2(dBih[2*t2 + 1] + dBhh[2*t2 + 1]);
    } else { bd0 = 0ull; bd1 = 0ull; }
    for (int idx = tid; idx < 64 * 32; idx += NT){
        int o = idx & 31, k2 = idx >> 5;
        fcW2[idx] = pack2(fcW[o * Hv + 2*k2], fcW[o * Hv + 2*k2 + 1]);
    }
    float fcbv = (tid < Iv * NB) ? fcB[tid & 31] : 0.f;
    float* outbase = out + (size_t)(bbase + (tid >> 5)) * Sv * Iv + (tid & 31);
    // hs4/hs2d hold enc_h; cs holds enc_c (never modified in decoder)
    __syncthreads();

    // ======================= decoder loop =======================
    for (int t = 0; t < Sv; t++){
        ull p00 = bd0, p01 = bd0, p10 = bd1, p11 = bd1;
        ull q0 = 0ull, q1 = 0ull, q2 = 0ull, q3 = 0ull;

        if (!half){
            #pragma unroll 8
            for (int j = 0; j < 32; j++)
                MAC4(hs4 + j * NB, wp + j * Gv);
        } else {
            #pragma unroll 8
            for (int j = 0; j < 32; j++)
                MAC4(hs4 + (64 + j) * NB, wp + (32 + j) * Gv);
        }
        #pragma unroll
        for (int kk = 0; kk < KRv; kk++){
            ulonglong2 d01 = *(const ulonglong2*)(hs2d + (kbd + kk) * NB);
            ulonglong2 d23 = *(const ulonglong2*)(hs2d + (kbd + kk) * NB + 2);
            ffma2(q0, d01.x, wr[kk]); ffma2(q1, d01.y, wr[kk]);
            ffma2(q2, d23.x, wr[kk]); ffma2(q3, d23.y, wr[kk]);
        }
        float s0[4], s1[4];
        unpack2(p00, s0[0], s0[1]); unpack2(p01, s0[2], s0[3]);
        unpack2(p10, s1[0], s1[1]); unpack2(p11, s1[2], s1[3]);
        {   float u0, u1;
            unpack2(q0, u0, u1); s0[0] += u0; s1[0] += u1;
            unpack2(q1, u0, u1); s0[1] += u0; s1[1] += u1;
            unpack2(q2, u0, u1); s0[2] += u0; s1[2] += u1;
            unpack2(q3, u0, u1); s0[3] += u0; s1[3] += u1; }
        pact[tid]       = make_float4(s0[0], s1[0], s0[1], s1[1]);
        pact[512 + tid] = make_float4(s0[2], s1[2], s0[3], s1[3]);
        __syncthreads();                                   // B2
        {
            float4 pr = pact[half * 512 + (tid ^ 256)];
            int b0i = half * 2;
            float m00 = s0[b0i]     + pr.x, m10 = s1[b0i]     + pr.y;
            float m01 = s0[b0i + 1] + pr.z, m11 = s1[b0i + 1] + pr.w;
            float v00, v10, v01, v11;
            if (gt == 2){ v00 = tanh_(m00); v10 = tanh_(m10); v01 = tanh_(m01); v11 = tanh_(m11); }
            else        { v00 = sig_(m00);  v10 = sig_(m10);  v01 = sig_(m01);  v11 = sig_(m11);  }
            *(float2*)(gact + b0i * Gv + 2*t2)       = make_float2(v00, v10);
            *(float2*)(gact + (b0i + 1) * Gv + 2*t2) = make_float2(v01, v11);
        }
        __syncthreads();                                   // B3
        {   // h update: cell input is ALWAYS enc_c (cs), never written back
            int b = tid >> 7, u = tid & (Hv - 1);
            const float* gb = gact + b * Gv;
            float iv = gb[u], fv = gb[Hv + u], gvv = gb[2*Hv + u], ov = gb[3*Hv + u];
            float cn = fv * cs[b * Hv + u] + iv * gvv;
            float hn = ov * tanh_(cn);
            hs4[u * NB + b]  = hn;
            hs2d[u * NB + b] = pack2(hn, hn);
            hsp[b * Hv + u]  = hn;
        }
        if (t == 0){
            // in place: Whh -> Whh + Wih (steps >=1 have inp == h)
            for (int idx = tid; idx < Gv * 64; idx += NT){
                int r = idx >> 9, g = idx & (Gv - 1);
                Ws[idx] += (r < 32) ? dWih[g * Hv + r] : dWih[g * Hv + (r + 32)];
            }
            #pragma unroll
            for (int kk = 0; kk < KRv; kk++){
                float w0, w1; unpack2(wr[kk], w0, w1);
                w0 += dWih[(2*t2) * Hv + kbd + kk];
                w1 += dWih[(2*t2 + 1) * Hv + kbd + kk];
                wr[kk] = pack2(w0, w1);
            }
        }
        __syncthreads();                                   // B4 (hsp->fc, Ws add->next read)
        if (tid < Iv * NB){
            int b = tid >> 5, o = tid & 31;
            ull s = 0ull;
            #pragma unroll
            for (int k2 = 0; k2 < Hv / 2; k2++){
                ull h2 = *(const ull*)(hsp + b * Hv + 2*k2);
                ffma2(s, h2, fcW2[k2 * 32 + o]);
            }
            float sa, sb; unpack2(s, sa, sb);
            outbase[t * Iv] = sa + sb + fcbv;
        }
        // fc reads complete before these threads reach next B2; writers of
        // hsp (next step) are gated behind next B3 -> safe
    }
}

extern "C" void kernel_launch(void* const* d_in, const int* in_sizes, int n_in,
                              void* d_out, int out_size)
{
    const float* x    = (const float*)d_in[0];
    const float* eWih = (const float*)d_in[1];
    const float* eWhh = (const float*)d_in[2];
    const float* eBih = (const float*)d_in[3];
    const float* eBhh = (const float*)d_in[4];
    const float* dWih = (const float*)d_in[5];
    const float* dWhh = (const float*)d_in[6];
    const float* dBih = (const float*)d_in[7];
    const float* dBhh = (const float*)d_in[8];
    const float* fcW  = (const float*)d_in[9];
    const float* fcB  = (const float*)d_in[10];
    float* out = (float*)d_out;

    cudaFuncSetAttribute(lstm_ae_kernel,
                         cudaFuncAttributeMaxDynamicSharedMemorySize, SMEM_BYTES);
    lstm_ae_kernel<<<NCTA, NT, SMEM_BYTES>>>(
        x, eWih, eWhh, eBih, eBhh, dWih, dWhh, dBih, dBhh, fcW, fcB, out);
}